// round 3
// baseline (speedup 1.0000x reference)
#include <cuda_runtime.h>
#include <math.h>

#define BB 4
#define NN 256
#define DMID 128
#define DE 8
#define HH 8
#define DD 16
#define LL 2
#define NROWS (BB*NN)   // 1024

// ---------------- scratch (no allocations allowed) ----------------
__device__ float g_q[NROWS*DMID];
__device__ float g_k[NROWS*DMID];
__device__ float g_v[NROWS*DMID];
__device__ float g_res[NROWS*DMID];
__device__ float g_att[NROWS*DMID];
__device__ float g_x[NROWS*DMID];
__device__ float g_means[NN];

// ---------------- projections: out = x @ W + b for q,k,v,res ----------------
__global__ void __launch_bounds__(128) proj_kernel(
    const float* __restrict__ x, int from_gx,
    const float* __restrict__ Wq, const float* __restrict__ bq,
    const float* __restrict__ Wk, const float* __restrict__ bk,
    const float* __restrict__ Wv, const float* __restrict__ bv,
    const float* __restrict__ Wr, const float* __restrict__ br)
{
    const float* W; const float* bias; float* out;
    switch (blockIdx.y) {
        case 0:  W = Wq; bias = bq; out = g_q;   break;
        case 1:  W = Wk; bias = bk; out = g_k;   break;
        case 2:  W = Wv; bias = bv; out = g_v;   break;
        default: W = Wr; bias = br; out = g_res; break;
    }
    __shared__ float xs[16][DMID];
    const int row0 = blockIdx.x * 16;
    const int t = threadIdx.x;           // 0..127 = output column
    const float* xsrc = from_gx ? g_x : x;
    #pragma unroll
    for (int r = 0; r < 16; r++)
        xs[r][t] = xsrc[(row0 + r) * DMID + t];
    __syncthreads();

    float acc[16];
    const float bv_ = bias[t];
    #pragma unroll
    for (int r = 0; r < 16; r++) acc[r] = bv_;

    for (int kk = 0; kk < DMID; kk++) {
        float w = W[kk * DMID + t];      // coalesced
        #pragma unroll
        for (int r = 0; r < 16; r++)
            acc[r] = fmaf(xs[r][kk], w, acc[r]);   // xs broadcast
    }
    #pragma unroll
    for (int r = 0; r < 16; r++)
        out[(row0 + r) * DMID + t] = acc[r];
}

// ---------------- means[i] = mean_j sim[b=0,h=0,i,j] (pre-mask) ----------------
__global__ void __launch_bounds__(256) means_kernel(
    const float* __restrict__ edges,
    const float* __restrict__ We, const float* __restrict__ be)
{
    const int i = blockIdx.x;
    const int j = threadIdx.x;  // 0..255
    __shared__ float q0[DD];
    __shared__ float Wes[DE][DD];
    __shared__ float bes[DD];
    __shared__ float red[8];

    if (j < DD) { q0[j] = g_q[i * DMID + j]; bes[j] = be[j]; }
    if (j < DE * DD) Wes[j / DD][j % DD] = We[(j / DD) * DMID + (j % DD)];
    __syncthreads();

    const float4* ep = (const float4*)(edges + ((size_t)i * NN + j) * DE);
    float4 e0 = ep[0], e1 = ep[1];
    float ed[DE] = {e0.x, e0.y, e0.z, e0.w, e1.x, e1.y, e1.z, e1.w};
    const float* krow = g_k + j * DMID;   // b=0 rows

    float acc = 0.f;
    #pragma unroll
    for (int d = 0; d < DD; d++) {
        float e = bes[d];
        #pragma unroll
        for (int c = 0; c < DE; c++) e = fmaf(ed[c], Wes[c][d], e);
        acc = fmaf(q0[d], krow[d] + e, acc);
    }
    #pragma unroll
    for (int off = 16; off; off >>= 1)
        acc += __shfl_xor_sync(0xffffffffu, acc, off);
    if ((j & 31) == 0) red[j >> 5] = acc;
    __syncthreads();
    if (j == 0) {
        float s = 0.f;
        #pragma unroll
        for (int w = 0; w < 8; w++) s += red[w];
        g_means[i] = s * (0.25f / (float)NN);   // scale=1/sqrt(16), /N
    }
}

// ---------------- fused edge-proj + attention ----------------
__global__ void __launch_bounds__(128) attn_kernel(
    const float* __restrict__ edges, const float* __restrict__ adj,
    const float* __restrict__ We, const float* __restrict__ be)
{
    const int i = blockIdx.x;
    const int b = blockIdx.y;
    const int t = threadIdx.x;           // inner dim 0..127; head = t/16
    const int row = b * NN + i;

    // fold softmax scale (0.25) into q so the post-reduce math is exp(p - mean)
    const float qt = g_q[row * DMID + t] * 0.25f;
    float wec[DE];
    #pragma unroll
    for (int c = 0; c < DE; c++) wec[c] = We[c * DMID + t];   // coalesced
    const float bet = be[t];
    const float mean_i = g_means[i];

    const float* erow  = edges + (size_t)row * NN * DE;
    const float* arow  = adj   + ((size_t)b * NN + i) * NN;
    const float* kbase = g_k + (size_t)b * NN * DMID + t;
    const float* vbase = g_v + (size_t)b * NN * DMID + t;

    float acc = 0.f, wsum = 0.f;
    #pragma unroll 4
    for (int j = 0; j < NN; j++) {
        const float4* ep = (const float4*)(erow + j * DE);
        float4 e0 = ep[0], e1 = ep[1];
        float e = bet;
        e = fmaf(e0.x, wec[0], e); e = fmaf(e0.y, wec[1], e);
        e = fmaf(e0.z, wec[2], e); e = fmaf(e0.w, wec[3], e);
        e = fmaf(e1.x, wec[4], e); e = fmaf(e1.y, wec[5], e);
        e = fmaf(e1.z, wec[6], e); e = fmaf(e1.w, wec[7], e);

        const float kt = kbase[j * DMID];
        const float vt = vbase[j * DMID];

        float p = qt * (kt + e);
        p += __shfl_xor_sync(0xffffffffu, p, 8);
        p += __shfl_xor_sync(0xffffffffu, p, 4);
        p += __shfl_xor_sync(0xffffffffu, p, 2);
        p += __shfl_xor_sync(0xffffffffu, p, 1);

        const float w = __expf(p - mean_i) * arow[j];
        acc  = fmaf(w, vt + e, acc);
        wsum += w;
    }
    float s = (wsum == 0.f) ? 1.f : wsum;
    g_att[row * DMID + t] = acc / s;
}

// ---------------- gated residual + sigmoid gate + LN + ReLU ----------------
__global__ void __launch_bounds__(128) epilogue_kernel(
    const float* __restrict__ Wg, const float* __restrict__ lng,
    const float* __restrict__ lnb, float* __restrict__ xout, int to_gx)
{
    const int row = blockIdx.x;
    const int t = threadIdx.x;
    const float o = g_att[row * DMID + t];
    const float r = g_res[row * DMID + t];

    float p = o * Wg[t] + r * Wg[DMID + t] + (o - r) * Wg[2 * DMID + t];

    __shared__ float red[4], r1[4], r2[4];
    float sgate = p;
    #pragma unroll
    for (int off = 16; off; off >>= 1)
        sgate += __shfl_xor_sync(0xffffffffu, sgate, off);
    if ((t & 31) == 0) red[t >> 5] = sgate;
    __syncthreads();
    const float tot = red[0] + red[1] + red[2] + red[3];
    const float g = 1.f / (1.f + __expf(-tot));
    const float y = o * g + r * (1.f - g);

    float s1 = y, s2 = y * y;
    #pragma unroll
    for (int off = 16; off; off >>= 1) {
        s1 += __shfl_xor_sync(0xffffffffu, s1, off);
        s2 += __shfl_xor_sync(0xffffffffu, s2, off);
    }
    if ((t & 31) == 0) { r1[t >> 5] = s1; r2[t >> 5] = s2; }
    __syncthreads();
    const float mu = (r1[0] + r1[1] + r1[2] + r1[3]) * (1.f / DMID);
    const float m2 = (r2[0] + r2[1] + r2[2] + r2[3]) * (1.f / DMID);
    const float var = m2 - mu * mu;
    const float yn = (y - mu) * rsqrtf(var + 1e-5f) * lng[t] + lnb[t];
    const float res = fmaxf(yn, 0.f);

    if (to_gx) g_x[row * DMID + t] = res;
    else       xout[row * DMID + t] = res;
}

// ---------------- launcher ----------------
extern "C" void kernel_launch(void* const* d_in, const int* in_sizes, int n_in,
                              void* d_out, int out_size)
{
    const float* nodes = (const float*)d_in[0];
    const float* edges = (const float*)d_in[1];
    const float* adj   = (const float*)d_in[2];
    const float* Wq = (const float*)d_in[3];
    const float* bq = (const float*)d_in[4];
    const float* Wk = (const float*)d_in[5];
    const float* bk = (const float*)d_in[6];
    const float* Wv = (const float*)d_in[7];
    const float* bv = (const float*)d_in[8];
    const float* We = (const float*)d_in[9];
    const float* be = (const float*)d_in[10];
    const float* Wr = (const float*)d_in[11];
    const float* br = (const float*)d_in[12];
    const float* Wg = (const float*)d_in[13];
    const float* lng = (const float*)d_in[14];
    const float* lnb = (const float*)d_in[15];
    float* out = (float*)d_out;

    for (int l = 0; l < LL; l++) {
        const int wofs = l * DMID * DMID;   // 16384
        const int bofs = l * DMID;          // 128
        const int eofs = l * DE * DMID;     // 1024
        const int gofs = l * 3 * DMID;      // 384

        proj_kernel<<<dim3(NROWS / 16, 4), 128>>>(
            nodes, (l == 0) ? 0 : 1,
            Wq + wofs, bq + bofs, Wk + wofs, bk + bofs,
            Wv + wofs, bv + bofs, Wr + wofs, br + bofs);

        means_kernel<<<NN, 256>>>(edges, We + eofs, be + bofs);

        attn_kernel<<<dim3(NN, BB), 128>>>(edges, adj, We + eofs, be + bofs);

        epilogue_kernel<<<NROWS, 128>>>(
            Wg + gofs, lng + bofs, lnb + bofs, out, (l == LL - 1) ? 0 : 1);
    }
}